// round 14
// baseline (speedup 1.0000x reference)
#include <cuda_runtime.h>

#define NN 100000   // nodes
#define NPAD 100096 // padded node count
#define NE 500000   // edges
#define NH 4        // heads
#define HD 32       // output width
#define PROJ 128
#define U16 16      // folded edge-feature width

// score-fold layout inside edge smem (floats)
#define A_OFF     0            // 4*3*3 = 36  quadratic form (pre-scaled 1/sqrt(32))
#define LIN_OFF   36           // 4*3  = 12
#define S0_OFF    48           // 4
#define SCORE_SZ  52

// ---------------- device scratch (no allocations allowed) ----------------
__device__ __align__(16) float g_seg[NPAD * U16]; // zeroed by pack_setup each launch
__device__ __align__(16) float4 g_pos4[NN];       // padded positions for 1-LDG gathers

// ---------------- kernel 1: zero seg + pack positions ----------------
__global__ void __launch_bounds__(256) pack_setup_kernel(const float* __restrict__ pos) {
    const int gid = blockIdx.x * blockDim.x + threadIdx.x;
    const int gsz = gridDim.x * blockDim.x;

    // zero the accumulator (grid-stride, v4) — covers padded rows too
    float4* s4 = reinterpret_cast<float4*>(g_seg);
    const int n4 = NPAD * U16 / 4;
    const float4 z = make_float4(0.f, 0.f, 0.f, 0.f);
    for (int j = gid; j < n4; j += gsz) s4[j] = z;

    // pack positions into float4
    for (int j = gid; j < NN; j += gsz)
        g_pos4[j] = make_float4(__ldg(&pos[j * 3 + 0]),
                                __ldg(&pos[j * 3 + 1]),
                                __ldg(&pos[j * 3 + 2]), 0.f);
}

// ---------------- kernel 2: quad-per-edge scores + scatter (PDL secondary) ----------------
__device__ __forceinline__ void red_add_v4(float* p, float4 v) {
    asm volatile("red.global.add.v4.f32 [%0], {%1,%2,%3,%4};"
                 :: "l"(p), "f"(v.x), "f"(v.y), "f"(v.z), "f"(v.w)
                 : "memory");
}

// NE*4 = 2,000,000 threads; lane quads (aligned) own one edge, lane%4 = head.
// Preamble (pre-gridsync): per-block score-fold from raw weights + is64 sniff —
// depends only on harness inputs, overlaps pack_setup's tail.
__global__ void __launch_bounds__(256) edge_kernel(
        const int* __restrict__ eraw,
        const float* __restrict__ Wq, const float* __restrict__ bq,
        const float* __restrict__ Wk, const float* __restrict__ bk) {
    __shared__ float sp[SCORE_SZ];
    __shared__ int s_is64;

    const int t = threadIdx.x;
    const float inv = 0.17677669529663687f;  // 1/sqrt(32)

    if (t < NH * 9) {
        // A_h[i][j] = sum_d Wq[i, h*32+d] * Wk[j, h*32+d]   (scaled)
        int h = t / 9, ii = (t % 9) / 3, jj = t % 3;
        const float* wq = &Wq[ii * PROJ + h * HD];
        const float* wk = &Wk[jj * PROJ + h * HD];
        float acc[8];
#pragma unroll
        for (int k = 0; k < 8; k++) acc[k] = 0.f;
#pragma unroll
        for (int d = 0; d < HD; d += 8) {
#pragma unroll
            for (int k = 0; k < 8; k++)
                acc[k] = fmaf(__ldg(&wq[d + k]), __ldg(&wk[d + k]), acc[k]);
        }
        sp[A_OFF + t] = (((acc[0] + acc[1]) + (acc[2] + acc[3]))
                       + ((acc[4] + acc[5]) + (acc[6] + acc[7]))) * inv;
    } else if (t < 48) {
        // lin_h[i] = sum_d (Wq[i,hd]*bk[hd] + Wk[i,hd]*bq[hd])   (scaled)
        int idx = t - 36;
        int h = idx / 3, ii = idx % 3;
        const float* wq = &Wq[ii * PROJ + h * HD];
        const float* wk = &Wk[ii * PROJ + h * HD];
        const float* bqv = &bq[h * HD];
        const float* bkv = &bk[h * HD];
        float a0 = 0.f, a1 = 0.f, a2 = 0.f, a3 = 0.f;
#pragma unroll
        for (int d = 0; d < HD; d += 2) {
            a0 = fmaf(__ldg(&wq[d]),     __ldg(&bkv[d]),     a0);
            a1 = fmaf(__ldg(&wk[d]),     __ldg(&bqv[d]),     a1);
            a2 = fmaf(__ldg(&wq[d + 1]), __ldg(&bkv[d + 1]), a2);
            a3 = fmaf(__ldg(&wk[d + 1]), __ldg(&bqv[d + 1]), a3);
        }
        sp[LIN_OFF + idx] = ((a0 + a1) + (a2 + a3)) * inv;
    } else if (t < 52) {
        // s0_h = bq_h . bk_h  (scaled)
        int h = t - 48;
        const float* bqv = &bq[h * HD];
        const float* bkv = &bk[h * HD];
        float a0 = 0.f, a1 = 0.f;
#pragma unroll
        for (int d = 0; d < HD; d += 2) {
            a0 = fmaf(__ldg(&bqv[d]),     __ldg(&bkv[d]),     a0);
            a1 = fmaf(__ldg(&bqv[d + 1]), __ldg(&bkv[d + 1]), a1);
        }
        sp[S0_OFF + h] = (a0 + a1) * inv;
    } else if (t == 64) {
        // int64 edge_index: node ids < 1e5 -> every odd 32-bit word is 0.
        int acc = 0;
#pragma unroll
        for (int k = 0; k < 32; k++) acc |= __ldg(&eraw[2 * k + 1]);
        s_is64 = (acc == 0);
    }
    __syncthreads();

    // wait for pack_setup (g_pos4, g_seg zeros)
    cudaGridDependencySynchronize();

    const int gid = blockIdx.x * blockDim.x + threadIdx.x;
    const int e = gid >> 2;
    const int h = gid & 3;
    if (e >= NE) return;                   // NE*4 % 32 == 0 -> whole warps drop

    int row, col;
    if (s_is64) {
        const long long* p = reinterpret_cast<const long long*>(eraw);
        row = (int)__ldg(&p[e]);           // quad-same address -> merged
        col = (int)__ldg(&p[NE + e]);
    } else {
        row = __ldg(&eraw[e]);
        col = __ldg(&eraw[NE + e]);
    }

    float4 pr = g_pos4[row];
    float4 pc = g_pos4[col];
    const float r0 = pr.x - pc.x, r1 = pr.y - pc.y, r2 = pr.z - pc.z;

    // this lane's head score (folded quadratic form)
    const float* A = &sp[A_OFF + h * 9];
    float t0 = sp[LIN_OFF + h * 3 + 0];
    t0 = fmaf(A[0], r0, fmaf(A[1], r1, fmaf(A[2], r2, t0)));
    float t1 = sp[LIN_OFF + h * 3 + 1];
    t1 = fmaf(A[3], r0, fmaf(A[4], r1, fmaf(A[5], r2, t1)));
    float t2 = sp[LIN_OFF + h * 3 + 2];
    t2 = fmaf(A[6], r0, fmaf(A[7], r1, fmaf(A[8], r2, t2)));
    float s = fmaf(r0, t0, fmaf(r1, t1, fmaf(r2, t2, sp[S0_OFF + h])));

    // quad softmax (laneMask 1,2 stay inside aligned quads)
    const unsigned mask = 0xffffffffu;
    float mx = s;
    mx = fmaxf(mx, __shfl_xor_sync(mask, mx, 1));
    mx = fmaxf(mx, __shfl_xor_sync(mask, mx, 2));
    float a = __expf(s - mx);
    float den = a;
    den += __shfl_xor_sync(mask, den, 1);
    den += __shfl_xor_sync(mask, den, 2);
    float ah = a / den;

    // one red.v4 per lane; quad covers one contiguous 64B block of g_seg[col]
    red_add_v4(&g_seg[(size_t)col * U16 + h * 4],
               make_float4(ah * r0, ah * r1, ah * r2, ah));
}

// ---------------- kernel 3: per-node u@B + LN + SiLU (PDL secondary) ----------------
// Preamble: per-block B-fold + epilogue params from raw weights — depends only on
// harness inputs, overlaps edge_kernel's tail.
__global__ void __launch_bounds__(256) node_kernel(
        float* __restrict__ out,
        const float* __restrict__ Wv, const float* __restrict__ bv,
        const float* __restrict__ Wout, const float* __restrict__ bout,
        const float* __restrict__ gamma, const float* __restrict__ beta) {
    __shared__ __align__(16) float sB[U16 * HD];   // 512 floats
    __shared__ __align__(16) float sEpi[3 * HD];   // bout | gamma | beta

    const int t = threadIdx.x;
    // B fold: 2 outputs per thread, lane = o (coalesced Wout rows)
#pragma unroll
    for (int half = 0; half < 2; half++) {
        int idx = half * 256 + t;                  // 0..511
        int j = idx >> 5, o = idx & 31;
        int h = j >> 2, ii = j & 3;
        const float* wsrc = (ii < 3) ? &Wv[ii * PROJ + h * HD] : &bv[h * HD];
        const float* wo   = &Wout[(size_t)h * HD * HD + o];
        float acc[8];
#pragma unroll
        for (int k = 0; k < 8; k++) acc[k] = 0.f;
#pragma unroll
        for (int d = 0; d < HD; d += 8) {
#pragma unroll
            for (int k = 0; k < 8; k++)
                acc[k] = fmaf(__ldg(&wsrc[d + k]), __ldg(&wo[(d + k) * HD]), acc[k]);
        }
        sB[idx] = ((acc[0] + acc[1]) + (acc[2] + acc[3]))
                + ((acc[4] + acc[5]) + (acc[6] + acc[7]));
    }
    if (t < 3 * HD) {
        const float* src = (t < HD) ? &bout[t]
                         : (t < 2 * HD) ? &gamma[t - HD]
                         : &beta[t - 2 * HD];
        sEpi[t] = __ldg(src);
    }
    __syncthreads();

    // wait for edge_kernel's scatter into g_seg
    cudaGridDependencySynchronize();

    int gt   = blockIdx.x * blockDim.x + threadIdx.x;
    int pair = gt >> 2;
    int sub  = gt & 3;
    int n0   = pair * 2;          // NN is even -> n0, n0+1 both valid when n0 < NN
    bool valid = (n0 < NN);
    unsigned mask = 0xffffffffu;

    float s0[U16], s1[U16];
    if (valid) {
        const float4* p0 = reinterpret_cast<const float4*>(&g_seg[(size_t)n0 * U16]);
        const float4* p1 = reinterpret_cast<const float4*>(&g_seg[(size_t)(n0 + 1) * U16]);
#pragma unroll
        for (int k = 0; k < 4; k++) {
            float4 v = p0[k];
            s0[k*4+0]=v.x; s0[k*4+1]=v.y; s0[k*4+2]=v.z; s0[k*4+3]=v.w;
        }
#pragma unroll
        for (int k = 0; k < 4; k++) {
            float4 v = p1[k];
            s1[k*4+0]=v.x; s1[k*4+1]=v.y; s1[k*4+2]=v.z; s1[k*4+3]=v.w;
        }
    } else {
#pragma unroll
        for (int k = 0; k < U16; k++) { s0[k] = 0.f; s1[k] = 0.f; }
    }

    float rinv0 = 1.0f / fmaxf(s0[3] + s0[7] + s0[11] + s0[15], 1.0f);
    float rinv1 = 1.0f / fmaxf(s1[3] + s1[7] + s1[11] + s1[15], 1.0f);

    const int o0 = sub * 8;
    float y0[8], y1[8];
#pragma unroll
    for (int c = 0; c < 8; c++) { y0[c] = 0.f; y1[c] = 0.f; }
#pragma unroll
    for (int j = 0; j < U16; j++) {
        const float4* brow = reinterpret_cast<const float4*>(&sB[j * HD + o0]);
        float4 b0 = brow[0], b1 = brow[1];
        float a0 = s0[j], a1 = s1[j];
        y0[0]=fmaf(a0,b0.x,y0[0]); y0[1]=fmaf(a0,b0.y,y0[1]);
        y0[2]=fmaf(a0,b0.z,y0[2]); y0[3]=fmaf(a0,b0.w,y0[3]);
        y0[4]=fmaf(a0,b1.x,y0[4]); y0[5]=fmaf(a0,b1.y,y0[5]);
        y0[6]=fmaf(a0,b1.z,y0[6]); y0[7]=fmaf(a0,b1.w,y0[7]);
        y1[0]=fmaf(a1,b0.x,y1[0]); y1[1]=fmaf(a1,b0.y,y1[1]);
        y1[2]=fmaf(a1,b0.z,y1[2]); y1[3]=fmaf(a1,b0.w,y1[3]);
        y1[4]=fmaf(a1,b1.x,y1[4]); y1[5]=fmaf(a1,b1.y,y1[5]);
        y1[6]=fmaf(a1,b1.z,y1[6]); y1[7]=fmaf(a1,b1.w,y1[7]);
    }

    float sum0 = 0.f, sum1 = 0.f;
#pragma unroll
    for (int c = 0; c < 8; c++) {
        y0[c] = fmaf(y0[c], rinv0, sEpi[o0 + c]);
        y1[c] = fmaf(y1[c], rinv1, sEpi[o0 + c]);
        sum0 += y0[c]; sum1 += y1[c];
    }
    sum0 += __shfl_xor_sync(mask, sum0, 1);
    sum0 += __shfl_xor_sync(mask, sum0, 2);
    sum1 += __shfl_xor_sync(mask, sum1, 1);
    sum1 += __shfl_xor_sync(mask, sum1, 2);
    float mu0 = sum0 * (1.0f / 32.0f);
    float mu1 = sum1 * (1.0f / 32.0f);

    float sq0 = 0.f, sq1 = 0.f;
#pragma unroll
    for (int c = 0; c < 8; c++) {
        float d0 = y0[c] - mu0; sq0 = fmaf(d0, d0, sq0);
        float d1 = y1[c] - mu1; sq1 = fmaf(d1, d1, sq1);
    }
    sq0 += __shfl_xor_sync(mask, sq0, 1);
    sq0 += __shfl_xor_sync(mask, sq0, 2);
    sq1 += __shfl_xor_sync(mask, sq1, 1);
    sq1 += __shfl_xor_sync(mask, sq1, 2);
    float sf0 = rsqrtf(sq0 * (1.0f / 32.0f) + 1e-5f);
    float sf1 = rsqrtf(sq1 * (1.0f / 32.0f) + 1e-5f);

    if (!valid) return;

    float4* op0 = reinterpret_cast<float4*>(&out[(size_t)n0 * HD + o0]);
    float4* op1 = reinterpret_cast<float4*>(&out[(size_t)(n0 + 1) * HD + o0]);
#pragma unroll
    for (int k = 0; k < 2; k++) {
        float4 v0, v1;
        float* vp0 = &v0.x;
        float* vp1 = &v1.x;
#pragma unroll
        for (int c = 0; c < 4; c++) {
            int o = o0 + k * 4 + c;
            float g = sEpi[HD + o], bt = sEpi[2 * HD + o];
            float x0 = (y0[k*4+c] - mu0) * sf0 * g + bt;
            float x1 = (y1[k*4+c] - mu1) * sf1 * g + bt;
            vp0[c] = x0 / (1.0f + __expf(-x0));
            vp1[c] = x1 / (1.0f + __expf(-x1));
        }
        op0[k] = v0;
        op1[k] = v1;
    }
}

// ---------------- launch ----------------
extern "C" void kernel_launch(void* const* d_in, const int* in_sizes, int n_in,
                              void* d_out, int out_size) {
    const float* pos   = (const float*)d_in[0];
    const int*   edge  = (const int*)d_in[1];
    const float* Wq    = (const float*)d_in[2];
    const float* bq    = (const float*)d_in[3];
    const float* Wk    = (const float*)d_in[4];
    const float* bk    = (const float*)d_in[5];
    const float* Wv    = (const float*)d_in[6];
    const float* bv    = (const float*)d_in[7];
    const float* Wout  = (const float*)d_in[8];
    const float* bout  = (const float*)d_in[9];
    const float* gamma = (const float*)d_in[10];
    const float* beta  = (const float*)d_in[11];
    float* out = (float*)d_out;

    pack_setup_kernel<<<304, 256>>>(pos);

    // PDL: edge preamble (score folds) overlaps pack; node preamble (B fold)
    // overlaps edge's tail.
    cudaLaunchAttribute pdl[1];
    pdl[0].id = cudaLaunchAttributeProgrammaticStreamSerialization;
    pdl[0].val.programmaticStreamSerializationAllowed = 1;

    {
        cudaLaunchConfig_t cfg = {};
        cfg.gridDim  = dim3((NE * 4 + 255) / 256, 1, 1);
        cfg.blockDim = dim3(256, 1, 1);
        cfg.attrs = pdl;
        cfg.numAttrs = 1;
        cudaLaunchKernelEx(&cfg, edge_kernel, edge, Wq, bq, Wk, bk);
    }
    {
        cudaLaunchConfig_t cfg = {};
        cfg.gridDim  = dim3((NN / 2 * 4 + 255) / 256, 1, 1);
        cfg.blockDim = dim3(256, 1, 1);
        cfg.attrs = pdl;
        cfg.numAttrs = 1;
        cudaLaunchKernelEx(&cfg, node_kernel, out, Wv, bv, Wout, bout, gamma, beta);
    }
}

// round 15
// speedup vs baseline: 2.5491x; 2.5491x over previous
#include <cuda_runtime.h>

#define NN 100000   // nodes
#define NPAD 100096 // padded node count
#define NE 500000   // edges
#define NH 4        // heads
#define HD 32       // output width
#define PROJ 128
#define U16 16      // folded edge-feature width

// folded-parameter layout inside g_fold (floats)
#define A_OFF     0            // 4*3*3 = 36  quadratic form (pre-scaled 1/sqrt(32))
#define LIN_OFF   36           // 4*3  = 12
#define S0_OFF    48           // 4
#define SCORE_SZ  52
#define B_OFF     52           // 16*32 = 512
#define BOUT_OFF  564          // 32
#define GAMMA_OFF 596          // 32
#define BETA_OFF  628          // 32
#define FOLD_SZ   660

// ---------------- device scratch (no allocations allowed) ----------------
// g_seg starts zeroed (static init); node_kernel re-zeros each row after
// consuming it, so every edge_kernel launch sees zeros (R6-proven protocol).
__device__ __align__(16) float g_seg[NPAD * U16];
__device__ __align__(16) float4 g_pos4[NN];       // padded positions for 1-LDG gathers
__device__ __align__(16) float g_fold[FOLD_SZ];   // folded params
__device__ int   g_is64;                          // edge_index dtype flag

// ---------------- kernel 1: pack positions + weight fold (single copy) ----------------
__global__ void __launch_bounds__(256) pack_setup_kernel(
        const float* __restrict__ pos,
        const int* __restrict__ eraw,
        const float* __restrict__ Wq, const float* __restrict__ bq,
        const float* __restrict__ Wk, const float* __restrict__ bk,
        const float* __restrict__ Wv, const float* __restrict__ bv,
        const float* __restrict__ Wout, const float* __restrict__ bout,
        const float* __restrict__ gamma, const float* __restrict__ beta) {
    const int gid = blockIdx.x * blockDim.x + threadIdx.x;
    const int gsz = gridDim.x * blockDim.x;

    // pack positions into float4
    for (int j = gid; j < NN; j += gsz)
        g_pos4[j] = make_float4(__ldg(&pos[j * 3 + 0]),
                                __ldg(&pos[j * 3 + 1]),
                                __ldg(&pos[j * 3 + 2]), 0.f);

    const int t = threadIdx.x;
    const float inv = 0.17677669529663687f;  // 1/sqrt(32)

    if (blockIdx.x < 2) {
        // ---- B fold: one thread per output, lane = o (coalesced Wout rows) ----
        int idx = blockIdx.x * 256 + t;           // 0..511
        int j = idx >> 5, o = idx & 31;
        int h = j >> 2, ii = j & 3;
        const float* wsrc = (ii < 3) ? &Wv[ii * PROJ + h * HD] : &bv[h * HD];
        const float* wo   = &Wout[(size_t)h * HD * HD + o];
        float acc[8];
#pragma unroll
        for (int k = 0; k < 8; k++) acc[k] = 0.f;
#pragma unroll
        for (int d = 0; d < HD; d += 8) {
#pragma unroll
            for (int k = 0; k < 8; k++)
                acc[k] = fmaf(__ldg(&wsrc[d + k]), __ldg(&wo[(d + k) * HD]), acc[k]);
        }
        g_fold[B_OFF + idx] = ((acc[0] + acc[1]) + (acc[2] + acc[3]))
                            + ((acc[4] + acc[5]) + (acc[6] + acc[7]));
    } else if (blockIdx.x == 2) {
        if (t < NH * 9) {
            int h = t / 9, ii = (t % 9) / 3, jj = t % 3;
            const float* wq = &Wq[ii * PROJ + h * HD];
            const float* wk = &Wk[jj * PROJ + h * HD];
            float acc[8];
#pragma unroll
            for (int k = 0; k < 8; k++) acc[k] = 0.f;
#pragma unroll
            for (int d = 0; d < HD; d += 8) {
#pragma unroll
                for (int k = 0; k < 8; k++)
                    acc[k] = fmaf(__ldg(&wq[d + k]), __ldg(&wk[d + k]), acc[k]);
            }
            g_fold[A_OFF + t] = (((acc[0] + acc[1]) + (acc[2] + acc[3]))
                               + ((acc[4] + acc[5]) + (acc[6] + acc[7]))) * inv;
        } else if (t < 48) {
            int idx = t - 36;
            int h = idx / 3, ii = idx % 3;
            const float* wq = &Wq[ii * PROJ + h * HD];
            const float* wk = &Wk[ii * PROJ + h * HD];
            const float* bqv = &bq[h * HD];
            const float* bkv = &bk[h * HD];
            float a0 = 0.f, a1 = 0.f, a2 = 0.f, a3 = 0.f;
#pragma unroll
            for (int d = 0; d < HD; d += 2) {
                a0 = fmaf(__ldg(&wq[d]),     __ldg(&bkv[d]),     a0);
                a1 = fmaf(__ldg(&wk[d]),     __ldg(&bqv[d]),     a1);
                a2 = fmaf(__ldg(&wq[d + 1]), __ldg(&bkv[d + 1]), a2);
                a3 = fmaf(__ldg(&wk[d + 1]), __ldg(&bqv[d + 1]), a3);
            }
            g_fold[LIN_OFF + idx] = ((a0 + a1) + (a2 + a3)) * inv;
        } else if (t < 52) {
            int h = t - 48;
            const float* bqv = &bq[h * HD];
            const float* bkv = &bk[h * HD];
            float a0 = 0.f, a1 = 0.f;
#pragma unroll
            for (int d = 0; d < HD; d += 2) {
                a0 = fmaf(__ldg(&bqv[d]),     __ldg(&bkv[d]),     a0);
                a1 = fmaf(__ldg(&bqv[d + 1]), __ldg(&bkv[d + 1]), a1);
            }
            g_fold[S0_OFF + h] = (a0 + a1) * inv;
        } else if (t >= 64 && t < 160) {
            int idx = t - 64;
            const float* src = (idx < HD) ? &bout[idx]
                             : (idx < 2 * HD) ? &gamma[idx - HD]
                             : &beta[idx - 2 * HD];
            g_fold[BOUT_OFF + idx] = __ldg(src);
        } else if (t == 192) {
            // int64 edge_index: node ids < 1e5 -> every odd 32-bit word is 0.
            int acc = 0;
#pragma unroll
            for (int k = 0; k < 32; k++) acc |= __ldg(&eraw[2 * k + 1]);
            g_is64 = (acc == 0);
        }
    }
}

// ---------------- kernel 2: quad-per-edge scores + scatter (PDL secondary) ----------------
__device__ __forceinline__ void red_add_v4(float* p, float4 v) {
    asm volatile("red.global.add.v4.f32 [%0], {%1,%2,%3,%4};"
                 :: "l"(p), "f"(v.x), "f"(v.y), "f"(v.z), "f"(v.w)
                 : "memory");
}

// NE*4 = 2,000,000 threads; lane quads (aligned) own one edge, lane%4 = head.
__global__ void __launch_bounds__(256) edge_kernel(const int* __restrict__ eraw) {
    __shared__ float sp[SCORE_SZ];

    const int gid = blockIdx.x * blockDim.x + threadIdx.x;
    const int e = gid >> 2;
    const int h = gid & 3;

    // wait for pack_setup's writes (g_fold, g_pos4, g_is64); g_seg zeros are
    // maintained by the previous launch's node_kernel.
    cudaGridDependencySynchronize();

    if (threadIdx.x < SCORE_SZ) sp[threadIdx.x] = g_fold[threadIdx.x];
    __syncthreads();

    if (e >= NE) return;                   // NE*4 % 32 == 0 -> whole warps drop

    int row, col;
    if (g_is64) {
        const long long* p = reinterpret_cast<const long long*>(eraw);
        row = (int)__ldg(&p[e]);           // quad-same address -> merged
        col = (int)__ldg(&p[NE + e]);
    } else {
        row = __ldg(&eraw[e]);
        col = __ldg(&eraw[NE + e]);
    }

    float4 pr = g_pos4[row];
    float4 pc = g_pos4[col];
    const float r0 = pr.x - pc.x, r1 = pr.y - pc.y, r2 = pr.z - pc.z;

    // this lane's head score (folded quadratic form)
    const float* A = &sp[A_OFF + h * 9];
    float t0 = sp[LIN_OFF + h * 3 + 0];
    t0 = fmaf(A[0], r0, fmaf(A[1], r1, fmaf(A[2], r2, t0)));
    float t1 = sp[LIN_OFF + h * 3 + 1];
    t1 = fmaf(A[3], r0, fmaf(A[4], r1, fmaf(A[5], r2, t1)));
    float t2 = sp[LIN_OFF + h * 3 + 2];
    t2 = fmaf(A[6], r0, fmaf(A[7], r1, fmaf(A[8], r2, t2)));
    float s = fmaf(r0, t0, fmaf(r1, t1, fmaf(r2, t2, sp[S0_OFF + h])));

    // quad softmax (laneMask 1,2 stay inside aligned quads)
    const unsigned mask = 0xffffffffu;
    float mx = s;
    mx = fmaxf(mx, __shfl_xor_sync(mask, mx, 1));
    mx = fmaxf(mx, __shfl_xor_sync(mask, mx, 2));
    float a = __expf(s - mx);
    float den = a;
    den += __shfl_xor_sync(mask, den, 1);
    den += __shfl_xor_sync(mask, den, 2);
    float ah = a / den;

    // one red.v4 per lane; quad covers one contiguous 64B block of g_seg[col]
    red_add_v4(&g_seg[(size_t)col * U16 + h * 4],
               make_float4(ah * r0, ah * r1, ah * r2, ah));
}

// ---------------- kernel 3: per-node u@B + LN + SiLU (PDL secondary) ----------------
__global__ void __launch_bounds__(256) node_kernel(float* __restrict__ out) {
    __shared__ __align__(16) float sB[U16 * HD];   // 512 floats
    __shared__ __align__(16) float sEpi[3 * HD];   // bout | gamma | beta

    // preamble: stage folded params (pack_setup completed before edge_kernel's
    // gridsync released; edge never writes g_fold) — overlaps edge's tail.
    for (int i = threadIdx.x; i < U16 * HD; i += 256) sB[i] = g_fold[B_OFF + i];
    for (int i = threadIdx.x; i < 3 * HD; i += 256)  sEpi[i] = g_fold[BOUT_OFF + i];
    __syncthreads();

    // wait for edge_kernel's scatter into g_seg
    cudaGridDependencySynchronize();

    int gt   = blockIdx.x * blockDim.x + threadIdx.x;
    int pair = gt >> 2;
    int sub  = gt & 3;
    int n0   = pair * 2;          // NN is even -> n0, n0+1 both valid when n0 < NN
    bool valid = (n0 < NN);
    unsigned mask = 0xffffffffu;

    float s0[U16], s1[U16];
    if (valid) {
        const float4* p0 = reinterpret_cast<const float4*>(&g_seg[(size_t)n0 * U16]);
        const float4* p1 = reinterpret_cast<const float4*>(&g_seg[(size_t)(n0 + 1) * U16]);
#pragma unroll
        for (int k = 0; k < 4; k++) {
            float4 v = p0[k];
            s0[k*4+0]=v.x; s0[k*4+1]=v.y; s0[k*4+2]=v.z; s0[k*4+3]=v.w;
        }
#pragma unroll
        for (int k = 0; k < 4; k++) {
            float4 v = p1[k];
            s1[k*4+0]=v.x; s1[k*4+1]=v.y; s1[k*4+2]=v.z; s1[k*4+3]=v.w;
        }
    } else {
#pragma unroll
        for (int k = 0; k < U16; k++) { s0[k] = 0.f; s1[k] = 0.f; }
    }

    // all quad reads of this pair done -> re-zero our slice for the next launch
    __syncwarp(mask);
    if (valid) {
        float4 z = make_float4(0.f, 0.f, 0.f, 0.f);
        reinterpret_cast<float4*>(&g_seg[(size_t)n0 * U16])[sub] = z;
        reinterpret_cast<float4*>(&g_seg[(size_t)(n0 + 1) * U16])[sub] = z;
    }

    float rinv0 = 1.0f / fmaxf(s0[3] + s0[7] + s0[11] + s0[15], 1.0f);
    float rinv1 = 1.0f / fmaxf(s1[3] + s1[7] + s1[11] + s1[15], 1.0f);

    const int o0 = sub * 8;
    float y0[8], y1[8];
#pragma unroll
    for (int c = 0; c < 8; c++) { y0[c] = 0.f; y1[c] = 0.f; }
#pragma unroll
    for (int j = 0; j < U16; j++) {
        const float4* brow = reinterpret_cast<const float4*>(&sB[j * HD + o0]);
        float4 b0 = brow[0], b1 = brow[1];
        float a0 = s0[j], a1 = s1[j];
        y0[0]=fmaf(a0,b0.x,y0[0]); y0[1]=fmaf(a0,b0.y,y0[1]);
        y0[2]=fmaf(a0,b0.z,y0[2]); y0[3]=fmaf(a0,b0.w,y0[3]);
        y0[4]=fmaf(a0,b1.x,y0[4]); y0[5]=fmaf(a0,b1.y,y0[5]);
        y0[6]=fmaf(a0,b1.z,y0[6]); y0[7]=fmaf(a0,b1.w,y0[7]);
        y1[0]=fmaf(a1,b0.x,y1[0]); y1[1]=fmaf(a1,b0.y,y1[1]);
        y1[2]=fmaf(a1,b0.z,y1[2]); y1[3]=fmaf(a1,b0.w,y1[3]);
        y1[4]=fmaf(a1,b1.x,y1[4]); y1[5]=fmaf(a1,b1.y,y1[5]);
        y1[6]=fmaf(a1,b1.z,y1[6]); y1[7]=fmaf(a1,b1.w,y1[7]);
    }

    float sum0 = 0.f, sum1 = 0.f;
#pragma unroll
    for (int c = 0; c < 8; c++) {
        y0[c] = fmaf(y0[c], rinv0, sEpi[o0 + c]);
        y1[c] = fmaf(y1[c], rinv1, sEpi[o0 + c]);
        sum0 += y0[c]; sum1 += y1[c];
    }
    sum0 += __shfl_xor_sync(mask, sum0, 1);
    sum0 += __shfl_xor_sync(mask, sum0, 2);
    sum1 += __shfl_xor_sync(mask, sum1, 1);
    sum1 += __shfl_xor_sync(mask, sum1, 2);
    float mu0 = sum0 * (1.0f / 32.0f);
    float mu1 = sum1 * (1.0f / 32.0f);

    float sq0 = 0.f, sq1 = 0.f;
#pragma unroll
    for (int c = 0; c < 8; c++) {
        float d0 = y0[c] - mu0; sq0 = fmaf(d0, d0, sq0);
        float d1 = y1[c] - mu1; sq1 = fmaf(d1, d1, sq1);
    }
    sq0 += __shfl_xor_sync(mask, sq0, 1);
    sq0 += __shfl_xor_sync(mask, sq0, 2);
    sq1 += __shfl_xor_sync(mask, sq1, 1);
    sq1 += __shfl_xor_sync(mask, sq1, 2);
    float sf0 = rsqrtf(sq0 * (1.0f / 32.0f) + 1e-5f);
    float sf1 = rsqrtf(sq1 * (1.0f / 32.0f) + 1e-5f);

    if (!valid) return;

    float4* op0 = reinterpret_cast<float4*>(&out[(size_t)n0 * HD + o0]);
    float4* op1 = reinterpret_cast<float4*>(&out[(size_t)(n0 + 1) * HD + o0]);
#pragma unroll
    for (int k = 0; k < 2; k++) {
        float4 v0, v1;
        float* vp0 = &v0.x;
        float* vp1 = &v1.x;
#pragma unroll
        for (int c = 0; c < 4; c++) {
            int o = o0 + k * 4 + c;
            float g = sEpi[HD + o], bt = sEpi[2 * HD + o];
            float x0 = (y0[k*4+c] - mu0) * sf0 * g + bt;
            float x1 = (y1[k*4+c] - mu1) * sf1 * g + bt;
            vp0[c] = x0 / (1.0f + __expf(-x0));
            vp1[c] = x1 / (1.0f + __expf(-x1));
        }
        op0[k] = v0;
        op1[k] = v1;
    }
}

// ---------------- launch ----------------
extern "C" void kernel_launch(void* const* d_in, const int* in_sizes, int n_in,
                              void* d_out, int out_size) {
    const float* pos   = (const float*)d_in[0];
    const int*   edge  = (const int*)d_in[1];
    const float* Wq    = (const float*)d_in[2];
    const float* bq    = (const float*)d_in[3];
    const float* Wk    = (const float*)d_in[4];
    const float* bk    = (const float*)d_in[5];
    const float* Wv    = (const float*)d_in[6];
    const float* bv    = (const float*)d_in[7];
    const float* Wout  = (const float*)d_in[8];
    const float* bout  = (const float*)d_in[9];
    const float* gamma = (const float*)d_in[10];
    const float* beta  = (const float*)d_in[11];
    float* out = (float*)d_out;

    pack_setup_kernel<<<304, 256>>>(pos, edge, Wq, bq, Wk, bk, Wv, bv,
                                    Wout, bout, gamma, beta);

    // PDL: edge overlaps pack's tail; node overlaps edge's tail.
    cudaLaunchAttribute pdl[1];
    pdl[0].id = cudaLaunchAttributeProgrammaticStreamSerialization;
    pdl[0].val.programmaticStreamSerializationAllowed = 1;

    {
        cudaLaunchConfig_t cfg = {};
        cfg.gridDim  = dim3((NE * 4 + 255) / 256, 1, 1);
        cfg.blockDim = dim3(256, 1, 1);
        cfg.attrs = pdl;
        cfg.numAttrs = 1;
        cudaLaunchKernelEx(&cfg, edge_kernel, edge);
    }
    {
        cudaLaunchConfig_t cfg = {};
        cfg.gridDim  = dim3((NN / 2 * 4 + 255) / 256, 1, 1);
        cfg.blockDim = dim3(256, 1, 1);
        cfg.attrs = pdl;
        cfg.numAttrs = 1;
        cudaLaunchKernelEx(&cfg, node_kernel, out);
    }
}

// round 16
// speedup vs baseline: 2.7257x; 1.0693x over previous
#include <cuda_runtime.h>

#define NN 100000   // nodes
#define NPAD 100096 // padded node count
#define NE 500000   // edges
#define NH 4        // heads
#define HD 32       // output width
#define PROJ 128
#define U16 16      // folded edge-feature width

// folded-parameter layout inside g_fold (floats)
#define A_OFF     0            // 4*3*3 = 36  quadratic form (pre-scaled 1/sqrt(32))
#define LIN_OFF   36           // 4*3  = 12
#define S0_OFF    48           // 4
#define SCORE_SZ  52
#define B_OFF     52           // 16*32 = 512
#define BOUT_OFF  564          // 32
#define GAMMA_OFF 596          // 32
#define BETA_OFF  628          // 32
#define FOLD_SZ   660

// ---------------- device scratch (no allocations allowed) ----------------
__device__ __align__(16) float g_seg[NPAD * U16]; // zeroed by pack_setup each launch
__device__ __align__(16) float4 g_pos4[NN];       // padded positions for 1-LDG gathers
__device__ __align__(16) float g_fold[FOLD_SZ];   // folded params
__device__ int   g_is64;                          // edge_index dtype flag

// ---------------- kernel 1: zero + vectorized pos-pack + folds (split blocks) ----------------
__global__ void __launch_bounds__(256) pack_setup_kernel(
        const float* __restrict__ pos,
        const int* __restrict__ eraw,
        const float* __restrict__ Wq, const float* __restrict__ bq,
        const float* __restrict__ Wk, const float* __restrict__ bk,
        const float* __restrict__ Wv, const float* __restrict__ bv,
        const float* __restrict__ Wout, const float* __restrict__ bout,
        const float* __restrict__ gamma, const float* __restrict__ beta) {
    const int t = threadIdx.x;
    const float inv = 0.17677669529663687f;  // 1/sqrt(32)

    if (blockIdx.x < 2) {
        // ---- B fold: one thread per output, lane = o (coalesced Wout rows) ----
        int idx = blockIdx.x * 256 + t;           // 0..511
        int j = idx >> 5, o = idx & 31;
        int h = j >> 2, ii = j & 3;
        const float* wsrc = (ii < 3) ? &Wv[ii * PROJ + h * HD] : &bv[h * HD];
        const float* wo   = &Wout[(size_t)h * HD * HD + o];
        float acc[8];
#pragma unroll
        for (int k = 0; k < 8; k++) acc[k] = 0.f;
#pragma unroll
        for (int d = 0; d < HD; d += 8) {
#pragma unroll
            for (int k = 0; k < 8; k++)
                acc[k] = fmaf(__ldg(&wsrc[d + k]), __ldg(&wo[(d + k) * HD]), acc[k]);
        }
        g_fold[B_OFF + idx] = ((acc[0] + acc[1]) + (acc[2] + acc[3]))
                            + ((acc[4] + acc[5]) + (acc[6] + acc[7]));
        return;
    }
    if (blockIdx.x == 2) {
        if (t < NH * 9) {
            int h = t / 9, ii = (t % 9) / 3, jj = t % 3;
            const float* wq = &Wq[ii * PROJ + h * HD];
            const float* wk = &Wk[jj * PROJ + h * HD];
            float acc[8];
#pragma unroll
            for (int k = 0; k < 8; k++) acc[k] = 0.f;
#pragma unroll
            for (int d = 0; d < HD; d += 8) {
#pragma unroll
                for (int k = 0; k < 8; k++)
                    acc[k] = fmaf(__ldg(&wq[d + k]), __ldg(&wk[d + k]), acc[k]);
            }
            g_fold[A_OFF + t] = (((acc[0] + acc[1]) + (acc[2] + acc[3]))
                               + ((acc[4] + acc[5]) + (acc[6] + acc[7]))) * inv;
        } else if (t < 48) {
            int idx = t - 36;
            int h = idx / 3, ii = idx % 3;
            const float* wq = &Wq[ii * PROJ + h * HD];
            const float* wk = &Wk[ii * PROJ + h * HD];
            const float* bqv = &bq[h * HD];
            const float* bkv = &bk[h * HD];
            float a0 = 0.f, a1 = 0.f, a2 = 0.f, a3 = 0.f;
#pragma unroll
            for (int d = 0; d < HD; d += 2) {
                a0 = fmaf(__ldg(&wq[d]),     __ldg(&bkv[d]),     a0);
                a1 = fmaf(__ldg(&wk[d]),     __ldg(&bqv[d]),     a1);
                a2 = fmaf(__ldg(&wq[d + 1]), __ldg(&bkv[d + 1]), a2);
                a3 = fmaf(__ldg(&wk[d + 1]), __ldg(&bqv[d + 1]), a3);
            }
            g_fold[LIN_OFF + idx] = ((a0 + a1) + (a2 + a3)) * inv;
        } else if (t < 52) {
            int h = t - 48;
            const float* bqv = &bq[h * HD];
            const float* bkv = &bk[h * HD];
            float a0 = 0.f, a1 = 0.f;
#pragma unroll
            for (int d = 0; d < HD; d += 2) {
                a0 = fmaf(__ldg(&bqv[d]),     __ldg(&bkv[d]),     a0);
                a1 = fmaf(__ldg(&bqv[d + 1]), __ldg(&bkv[d + 1]), a1);
            }
            g_fold[S0_OFF + h] = (a0 + a1) * inv;
        } else if (t >= 64 && t < 160) {
            int idx = t - 64;
            const float* src = (idx < HD) ? &bout[idx]
                             : (idx < 2 * HD) ? &gamma[idx - HD]
                             : &beta[idx - 2 * HD];
            g_fold[BOUT_OFF + idx] = __ldg(src);
        } else if (t == 192) {
            // int64 edge_index: node ids < 1e5 -> every odd 32-bit word is 0.
            int acc = 0;
#pragma unroll
            for (int k = 0; k < 32; k++) acc |= __ldg(&eraw[2 * k + 1]);
            g_is64 = (acc == 0);
        }
        return;
    }

    // ---- blocks >= 3: zero accumulator + vectorized pos-pack ----
    const int gid = (blockIdx.x - 3) * blockDim.x + t;
    const int gsz = (gridDim.x - 3) * blockDim.x;

    float4* s4 = reinterpret_cast<float4*>(g_seg);
    const int n4 = NPAD * U16 / 4;
    const float4 z = make_float4(0.f, 0.f, 0.f, 0.f);
    for (int j = gid; j < n4; j += gsz) s4[j] = z;

    // 4 nodes per thread: 3 coalesced float4 reads cover 4 positions
    const float4* pv = reinterpret_cast<const float4*>(pos);
    for (int j = gid; j < NN / 4; j += gsz) {
        float4 a = __ldg(&pv[j * 3 + 0]);
        float4 b = __ldg(&pv[j * 3 + 1]);
        float4 c = __ldg(&pv[j * 3 + 2]);
        g_pos4[j * 4 + 0] = make_float4(a.x, a.y, a.z, 0.f);
        g_pos4[j * 4 + 1] = make_float4(a.w, b.x, b.y, 0.f);
        g_pos4[j * 4 + 2] = make_float4(b.z, b.w, c.x, 0.f);
        g_pos4[j * 4 + 3] = make_float4(c.y, c.z, c.w, 0.f);
    }
}

// ---------------- kernel 2: quad-per-edge scores + scatter (PDL secondary) ----------------
__device__ __forceinline__ void red_add_v4(float* p, float4 v) {
    asm volatile("red.global.add.v4.f32 [%0], {%1,%2,%3,%4};"
                 :: "l"(p), "f"(v.x), "f"(v.y), "f"(v.z), "f"(v.w)
                 : "memory");
}

// NE*4 = 2,000,000 threads; lane quads (aligned) own one edge, lane%4 = head.
__global__ void __launch_bounds__(256) edge_kernel(const int* __restrict__ eraw) {
    __shared__ float sp[SCORE_SZ];

    const int gid = blockIdx.x * blockDim.x + threadIdx.x;
    const int e = gid >> 2;
    const int h = gid & 3;

    // wait for pack_setup's writes (g_fold, g_pos4, g_seg zeros, g_is64)
    cudaGridDependencySynchronize();

    if (threadIdx.x < SCORE_SZ) sp[threadIdx.x] = g_fold[threadIdx.x];
    __syncthreads();

    if (e >= NE) return;                   // NE*4 % 32 == 0 -> whole warps drop

    int row, col;
    if (g_is64) {
        const long long* p = reinterpret_cast<const long long*>(eraw);
        row = (int)__ldg(&p[e]);           // quad-same address -> merged
        col = (int)__ldg(&p[NE + e]);
    } else {
        row = __ldg(&eraw[e]);
        col = __ldg(&eraw[NE + e]);
    }

    float4 pr = g_pos4[row];
    float4 pc = g_pos4[col];
    const float r0 = pr.x - pc.x, r1 = pr.y - pc.y, r2 = pr.z - pc.z;

    // this lane's head score (folded quadratic form)
    const float* A = &sp[A_OFF + h * 9];
    float t0 = sp[LIN_OFF + h * 3 + 0];
    t0 = fmaf(A[0], r0, fmaf(A[1], r1, fmaf(A[2], r2, t0)));
    float t1 = sp[LIN_OFF + h * 3 + 1];
    t1 = fmaf(A[3], r0, fmaf(A[4], r1, fmaf(A[5], r2, t1)));
    float t2 = sp[LIN_OFF + h * 3 + 2];
    t2 = fmaf(A[6], r0, fmaf(A[7], r1, fmaf(A[8], r2, t2)));
    float s = fmaf(r0, t0, fmaf(r1, t1, fmaf(r2, t2, sp[S0_OFF + h])));

    // quad softmax (laneMask 1,2 stay inside aligned quads)
    const unsigned mask = 0xffffffffu;
    float mx = s;
    mx = fmaxf(mx, __shfl_xor_sync(mask, mx, 1));
    mx = fmaxf(mx, __shfl_xor_sync(mask, mx, 2));
    float a = __expf(s - mx);
    float den = a;
    den += __shfl_xor_sync(mask, den, 1);
    den += __shfl_xor_sync(mask, den, 2);
    float ah = a / den;

    // one red.v4 per lane; quad covers one contiguous 64B block of g_seg[col]
    red_add_v4(&g_seg[(size_t)col * U16 + h * 4],
               make_float4(ah * r0, ah * r1, ah * r2, ah));
}

// ---------------- kernel 3: per-node u@B + LN + SiLU (PDL secondary) ----------------
__global__ void __launch_bounds__(256) node_kernel(float* __restrict__ out) {
    __shared__ __align__(16) float sB[U16 * HD];   // 512 floats
    __shared__ __align__(16) float sEpi[3 * HD];   // bout | gamma | beta

    // preamble: stage folded params (pack_setup completed before edge_kernel's
    // gridsync released; edge never writes g_fold) — overlaps edge's tail.
    for (int i = threadIdx.x; i < U16 * HD; i += 256) sB[i] = g_fold[B_OFF + i];
    for (int i = threadIdx.x; i < 3 * HD; i += 256)  sEpi[i] = g_fold[BOUT_OFF + i];
    __syncthreads();

    // wait for edge_kernel's scatter into g_seg
    cudaGridDependencySynchronize();

    int gt   = blockIdx.x * blockDim.x + threadIdx.x;
    int pair = gt >> 2;
    int sub  = gt & 3;
    int n0   = pair * 2;          // NN is even -> n0, n0+1 both valid when n0 < NN
    bool valid = (n0 < NN);
    unsigned mask = 0xffffffffu;

    float s0[U16], s1[U16];
    if (valid) {
        const float4* p0 = reinterpret_cast<const float4*>(&g_seg[(size_t)n0 * U16]);
        const float4* p1 = reinterpret_cast<const float4*>(&g_seg[(size_t)(n0 + 1) * U16]);
#pragma unroll
        for (int k = 0; k < 4; k++) {
            float4 v = p0[k];
            s0[k*4+0]=v.x; s0[k*4+1]=v.y; s0[k*4+2]=v.z; s0[k*4+3]=v.w;
        }
#pragma unroll
        for (int k = 0; k < 4; k++) {
            float4 v = p1[k];
            s1[k*4+0]=v.x; s1[k*4+1]=v.y; s1[k*4+2]=v.z; s1[k*4+3]=v.w;
        }
    } else {
#pragma unroll
        for (int k = 0; k < U16; k++) { s0[k] = 0.f; s1[k] = 0.f; }
    }

    float rinv0 = 1.0f / fmaxf(s0[3] + s0[7] + s0[11] + s0[15], 1.0f);
    float rinv1 = 1.0f / fmaxf(s1[3] + s1[7] + s1[11] + s1[15], 1.0f);

    const int o0 = sub * 8;
    float y0[8], y1[8];
#pragma unroll
    for (int c = 0; c < 8; c++) { y0[c] = 0.f; y1[c] = 0.f; }
#pragma unroll
    for (int j = 0; j < U16; j++) {
        const float4* brow = reinterpret_cast<const float4*>(&sB[j * HD + o0]);
        float4 b0 = brow[0], b1 = brow[1];
        float a0 = s0[j], a1 = s1[j];
        y0[0]=fmaf(a0,b0.x,y0[0]); y0[1]=fmaf(a0,b0.y,y0[1]);
        y0[2]=fmaf(a0,b0.z,y0[2]); y0[3]=fmaf(a0,b0.w,y0[3]);
        y0[4]=fmaf(a0,b1.x,y0[4]); y0[5]=fmaf(a0,b1.y,y0[5]);
        y0[6]=fmaf(a0,b1.z,y0[6]); y0[7]=fmaf(a0,b1.w,y0[7]);
        y1[0]=fmaf(a1,b0.x,y1[0]); y1[1]=fmaf(a1,b0.y,y1[1]);
        y1[2]=fmaf(a1,b0.z,y1[2]); y1[3]=fmaf(a1,b0.w,y1[3]);
        y1[4]=fmaf(a1,b1.x,y1[4]); y1[5]=fmaf(a1,b1.y,y1[5]);
        y1[6]=fmaf(a1,b1.z,y1[6]); y1[7]=fmaf(a1,b1.w,y1[7]);
    }

    float sum0 = 0.f, sum1 = 0.f;
#pragma unroll
    for (int c = 0; c < 8; c++) {
        y0[c] = fmaf(y0[c], rinv0, sEpi[o0 + c]);
        y1[c] = fmaf(y1[c], rinv1, sEpi[o0 + c]);
        sum0 += y0[c]; sum1 += y1[c];
    }
    sum0 += __shfl_xor_sync(mask, sum0, 1);
    sum0 += __shfl_xor_sync(mask, sum0, 2);
    sum1 += __shfl_xor_sync(mask, sum1, 1);
    sum1 += __shfl_xor_sync(mask, sum1, 2);
    float mu0 = sum0 * (1.0f / 32.0f);
    float mu1 = sum1 * (1.0f / 32.0f);

    float sq0 = 0.f, sq1 = 0.f;
#pragma unroll
    for (int c = 0; c < 8; c++) {
        float d0 = y0[c] - mu0; sq0 = fmaf(d0, d0, sq0);
        float d1 = y1[c] - mu1; sq1 = fmaf(d1, d1, sq1);
    }
    sq0 += __shfl_xor_sync(mask, sq0, 1);
    sq0 += __shfl_xor_sync(mask, sq0, 2);
    sq1 += __shfl_xor_sync(mask, sq1, 1);
    sq1 += __shfl_xor_sync(mask, sq1, 2);
    float sf0 = rsqrtf(sq0 * (1.0f / 32.0f) + 1e-5f);
    float sf1 = rsqrtf(sq1 * (1.0f / 32.0f) + 1e-5f);

    if (!valid) return;

    float4* op0 = reinterpret_cast<float4*>(&out[(size_t)n0 * HD + o0]);
    float4* op1 = reinterpret_cast<float4*>(&out[(size_t)(n0 + 1) * HD + o0]);
#pragma unroll
    for (int k = 0; k < 2; k++) {
        float4 v0, v1;
        float* vp0 = &v0.x;
        float* vp1 = &v1.x;
#pragma unroll
        for (int c = 0; c < 4; c++) {
            int o = o0 + k * 4 + c;
            float g = sEpi[HD + o], bt = sEpi[2 * HD + o];
            float x0 = (y0[k*4+c] - mu0) * sf0 * g + bt;
            float x1 = (y1[k*4+c] - mu1) * sf1 * g + bt;
            vp0[c] = x0 / (1.0f + __expf(-x0));
            vp1[c] = x1 / (1.0f + __expf(-x1));
        }
        op0[k] = v0;
        op1[k] = v1;
    }
}

// ---------------- launch ----------------
extern "C" void kernel_launch(void* const* d_in, const int* in_sizes, int n_in,
                              void* d_out, int out_size) {
    const float* pos   = (const float*)d_in[0];
    const int*   edge  = (const int*)d_in[1];
    const float* Wq    = (const float*)d_in[2];
    const float* bq    = (const float*)d_in[3];
    const float* Wk    = (const float*)d_in[4];
    const float* bk    = (const float*)d_in[5];
    const float* Wv    = (const float*)d_in[6];
    const float* bv    = (const float*)d_in[7];
    const float* Wout  = (const float*)d_in[8];
    const float* bout  = (const float*)d_in[9];
    const float* gamma = (const float*)d_in[10];
    const float* beta  = (const float*)d_in[11];
    float* out = (float*)d_out;

    pack_setup_kernel<<<608, 256>>>(pos, edge, Wq, bq, Wk, bk, Wv, bv,
                                    Wout, bout, gamma, beta);

    // PDL: edge overlaps pack's tail; node overlaps edge's tail.
    cudaLaunchAttribute pdl[1];
    pdl[0].id = cudaLaunchAttributeProgrammaticStreamSerialization;
    pdl[0].val.programmaticStreamSerializationAllowed = 1;

    {
        cudaLaunchConfig_t cfg = {};
        cfg.gridDim  = dim3((NE * 4 + 255) / 256, 1, 1);
        cfg.blockDim = dim3(256, 1, 1);
        cfg.attrs = pdl;
        cfg.numAttrs = 1;
        cudaLaunchKernelEx(&cfg, edge_kernel, edge);
    }
    {
        cudaLaunchConfig_t cfg = {};
        cfg.gridDim  = dim3((NN / 2 * 4 + 255) / 256, 1, 1);
        cfg.blockDim = dim3(256, 1, 1);
        cfg.attrs = pdl;
        cfg.numAttrs = 1;
        cudaLaunchKernelEx(&cfg, node_kernel, out);
    }
}

// round 17
// speedup vs baseline: 2.9016x; 1.0645x over previous
#include <cuda_runtime.h>

#define NN 100000   // nodes
#define NPAD 100096 // padded node count
#define NE 500000   // edges
#define NH 4        // heads
#define HD 32       // output width
#define PROJ 128
#define U16 16      // folded edge-feature width

// folded-parameter layout inside g_fold (floats)
#define A_OFF     0            // 4*3*3 = 36  quadratic form (pre-scaled 1/sqrt(32))
#define LIN_OFF   36           // 4*3  = 12
#define S0_OFF    48           // 4
#define SCORE_SZ  52
#define B_OFF     52           // 16*32 = 512
#define BOUT_OFF  564          // 32
#define GAMMA_OFF 596          // 32
#define BETA_OFF  628          // 32
#define FOLD_SZ   660

// ---------------- device scratch (no allocations allowed) ----------------
__device__ __align__(16) float g_seg[NPAD * U16]; // zeroed by pack_setup each launch
__device__ __align__(16) float4 g_pos4[NN];       // padded positions for 1-LDG gathers
__device__ __align__(16) float g_fold[FOLD_SZ];   // folded params
__device__ int   g_is64;                          // edge_index dtype flag

// ---------------- kernel 1: zero + vectorized pos-pack + folds (split blocks) ----------------
__global__ void __launch_bounds__(256) pack_setup_kernel(
        const float* __restrict__ pos,
        const int* __restrict__ eraw,
        const float* __restrict__ Wq, const float* __restrict__ bq,
        const float* __restrict__ Wk, const float* __restrict__ bk,
        const float* __restrict__ Wv, const float* __restrict__ bv,
        const float* __restrict__ Wout, const float* __restrict__ bout,
        const float* __restrict__ gamma, const float* __restrict__ beta) {
    const int t = threadIdx.x;
    const float inv = 0.17677669529663687f;  // 1/sqrt(32)

    if (blockIdx.x < 2) {
        // ---- B fold: one thread per output, lane = o (coalesced Wout rows) ----
        int idx = blockIdx.x * 256 + t;           // 0..511
        int j = idx >> 5, o = idx & 31;
        int h = j >> 2, ii = j & 3;
        const float* wsrc = (ii < 3) ? &Wv[ii * PROJ + h * HD] : &bv[h * HD];
        const float* wo   = &Wout[(size_t)h * HD * HD + o];
        float acc[8];
#pragma unroll
        for (int k = 0; k < 8; k++) acc[k] = 0.f;
#pragma unroll
        for (int d = 0; d < HD; d += 8) {
#pragma unroll
            for (int k = 0; k < 8; k++)
                acc[k] = fmaf(__ldg(&wsrc[d + k]), __ldg(&wo[(d + k) * HD]), acc[k]);
        }
        g_fold[B_OFF + idx] = ((acc[0] + acc[1]) + (acc[2] + acc[3]))
                            + ((acc[4] + acc[5]) + (acc[6] + acc[7]));
        return;
    }
    if (blockIdx.x == 2) {
        if (t < NH * 9) {
            int h = t / 9, ii = (t % 9) / 3, jj = t % 3;
            const float* wq = &Wq[ii * PROJ + h * HD];
            const float* wk = &Wk[jj * PROJ + h * HD];
            float acc[8];
#pragma unroll
            for (int k = 0; k < 8; k++) acc[k] = 0.f;
#pragma unroll
            for (int d = 0; d < HD; d += 8) {
#pragma unroll
                for (int k = 0; k < 8; k++)
                    acc[k] = fmaf(__ldg(&wq[d + k]), __ldg(&wk[d + k]), acc[k]);
            }
            g_fold[A_OFF + t] = (((acc[0] + acc[1]) + (acc[2] + acc[3]))
                               + ((acc[4] + acc[5]) + (acc[6] + acc[7]))) * inv;
        } else if (t < 48) {
            int idx = t - 36;
            int h = idx / 3, ii = idx % 3;
            const float* wq = &Wq[ii * PROJ + h * HD];
            const float* wk = &Wk[ii * PROJ + h * HD];
            const float* bqv = &bq[h * HD];
            const float* bkv = &bk[h * HD];
            float a0 = 0.f, a1 = 0.f, a2 = 0.f, a3 = 0.f;
#pragma unroll
            for (int d = 0; d < HD; d += 2) {
                a0 = fmaf(__ldg(&wq[d]),     __ldg(&bkv[d]),     a0);
                a1 = fmaf(__ldg(&wk[d]),     __ldg(&bqv[d]),     a1);
                a2 = fmaf(__ldg(&wq[d + 1]), __ldg(&bkv[d + 1]), a2);
                a3 = fmaf(__ldg(&wk[d + 1]), __ldg(&bqv[d + 1]), a3);
            }
            g_fold[LIN_OFF + idx] = ((a0 + a1) + (a2 + a3)) * inv;
        } else if (t < 52) {
            int h = t - 48;
            const float* bqv = &bq[h * HD];
            const float* bkv = &bk[h * HD];
            float a0 = 0.f, a1 = 0.f;
#pragma unroll
            for (int d = 0; d < HD; d += 2) {
                a0 = fmaf(__ldg(&bqv[d]),     __ldg(&bkv[d]),     a0);
                a1 = fmaf(__ldg(&bqv[d + 1]), __ldg(&bkv[d + 1]), a1);
            }
            g_fold[S0_OFF + h] = (a0 + a1) * inv;
        } else if (t >= 64 && t < 160) {
            int idx = t - 64;
            const float* src = (idx < HD) ? &bout[idx]
                             : (idx < 2 * HD) ? &gamma[idx - HD]
                             : &beta[idx - 2 * HD];
            g_fold[BOUT_OFF + idx] = __ldg(src);
        } else if (t == 192) {
            // int64 edge_index: node ids < 1e5 -> every odd 32-bit word is 0.
            int acc = 0;
#pragma unroll
            for (int k = 0; k < 32; k++) acc |= __ldg(&eraw[2 * k + 1]);
            g_is64 = (acc == 0);
        }
        return;
    }

    // ---- blocks >= 3: zero accumulator + vectorized pos-pack ----
    const int gid = (blockIdx.x - 3) * blockDim.x + t;
    const int gsz = (gridDim.x - 3) * blockDim.x;

    float4* s4 = reinterpret_cast<float4*>(g_seg);
    const int n4 = NPAD * U16 / 4;
    const float4 z = make_float4(0.f, 0.f, 0.f, 0.f);
    for (int j = gid; j < n4; j += gsz) s4[j] = z;

    // 4 nodes per thread: 3 coalesced float4 reads cover 4 positions
    const float4* pv = reinterpret_cast<const float4*>(pos);
    for (int j = gid; j < NN / 4; j += gsz) {
        float4 a = __ldg(&pv[j * 3 + 0]);
        float4 b = __ldg(&pv[j * 3 + 1]);
        float4 c = __ldg(&pv[j * 3 + 2]);
        g_pos4[j * 4 + 0] = make_float4(a.x, a.y, a.z, 0.f);
        g_pos4[j * 4 + 1] = make_float4(a.w, b.x, b.y, 0.f);
        g_pos4[j * 4 + 2] = make_float4(b.z, b.w, c.x, 0.f);
        g_pos4[j * 4 + 3] = make_float4(c.y, c.z, c.w, 0.f);
    }
}

// ---------------- kernel 2: quad-per-head, 2 edges/thread (PDL secondary) ----------------
__device__ __forceinline__ void red_add_v4(float* p, float4 v) {
    asm volatile("red.global.add.v4.f32 [%0], {%1,%2,%3,%4};"
                 :: "l"(p), "f"(v.x), "f"(v.y), "f"(v.z), "f"(v.w)
                 : "memory");
}

// 1M threads; aligned lane-quad q handles edges {2q, 2q+1}, lane%4 = head h.
// Scores are bounded (|s| << 80), so exp without max-subtraction is safe.
__global__ void __launch_bounds__(256) edge_kernel(const int* __restrict__ eraw) {
    __shared__ float sp[SCORE_SZ];

    const int gid = blockIdx.x * blockDim.x + threadIdx.x;
    const int q = gid >> 2;          // edge pair
    const int h = gid & 3;           // head
    const int e0 = q * 2;

    // wait for pack_setup's writes (g_fold, g_pos4, g_seg zeros, g_is64)
    cudaGridDependencySynchronize();

    if (threadIdx.x < SCORE_SZ) sp[threadIdx.x] = g_fold[threadIdx.x];
    __syncthreads();

    if (e0 >= NE) return;            // (NE/2)*4 % 32 == 0 -> whole warps drop

    int row0, col0, row1, col1;
    if (g_is64) {
        const longlong2* p = reinterpret_cast<const longlong2*>(eraw);
        longlong2 rw = __ldg(&p[q]);             // rows e0, e0+1 (quad-uniform)
        longlong2 cl = __ldg(&p[(NE >> 1) + q]); // cols e0, e0+1
        row0 = (int)rw.x; row1 = (int)rw.y;
        col0 = (int)cl.x; col1 = (int)cl.y;
    } else {
        const int2* p = reinterpret_cast<const int2*>(eraw);
        int2 rw = __ldg(&p[q]);
        int2 cl = __ldg(&p[(NE >> 1) + q]);
        row0 = rw.x; row1 = rw.y;
        col0 = cl.x; col1 = cl.y;
    }

    // 4 independent gathers -> MLP 4
    float4 pr0 = g_pos4[row0];
    float4 pc0 = g_pos4[col0];
    float4 pr1 = g_pos4[row1];
    float4 pc1 = g_pos4[col1];

    const float a0x = pr0.x - pc0.x, a0y = pr0.y - pc0.y, a0z = pr0.z - pc0.z;
    const float a1x = pr1.x - pc1.x, a1y = pr1.y - pc1.y, a1z = pr1.z - pc1.z;

    // this lane's head score for both edges (folded quadratic form)
    const float* A = &sp[A_OFF + h * 9];
    const float l0 = sp[LIN_OFF + h * 3 + 0];
    const float l1 = sp[LIN_OFF + h * 3 + 1];
    const float l2 = sp[LIN_OFF + h * 3 + 2];
    const float c0 = sp[S0_OFF + h];

    float t00 = fmaf(A[0], a0x, fmaf(A[1], a0y, fmaf(A[2], a0z, l0)));
    float t01 = fmaf(A[3], a0x, fmaf(A[4], a0y, fmaf(A[5], a0z, l1)));
    float t02 = fmaf(A[6], a0x, fmaf(A[7], a0y, fmaf(A[8], a0z, l2)));
    float s0  = fmaf(a0x, t00, fmaf(a0y, t01, fmaf(a0z, t02, c0)));

    float t10 = fmaf(A[0], a1x, fmaf(A[1], a1y, fmaf(A[2], a1z, l0)));
    float t11 = fmaf(A[3], a1x, fmaf(A[4], a1y, fmaf(A[5], a1z, l1)));
    float t12 = fmaf(A[6], a1x, fmaf(A[7], a1y, fmaf(A[8], a1z, l2)));
    float s1  = fmaf(a1x, t10, fmaf(a1y, t11, fmaf(a1z, t12, c0)));

    // quad softmax without max-subtraction (scores bounded)
    const unsigned mask = 0xffffffffu;
    float ex0 = __expf(s0);
    float ex1 = __expf(s1);
    float d0 = ex0, d1 = ex1;
    d0 += __shfl_xor_sync(mask, d0, 1);
    d1 += __shfl_xor_sync(mask, d1, 1);
    d0 += __shfl_xor_sync(mask, d0, 2);
    d1 += __shfl_xor_sync(mask, d1, 2);
    float ah0 = ex0 / d0;
    float ah1 = ex1 / d1;

    // one red.v4 per edge; quad covers one contiguous 64B block of g_seg[col]
    red_add_v4(&g_seg[(size_t)col0 * U16 + h * 4],
               make_float4(ah0 * a0x, ah0 * a0y, ah0 * a0z, ah0));
    red_add_v4(&g_seg[(size_t)col1 * U16 + h * 4],
               make_float4(ah1 * a1x, ah1 * a1y, ah1 * a1z, ah1));
}

// ---------------- kernel 3: per-node u@B + LN + SiLU (PDL secondary) ----------------
__global__ void __launch_bounds__(256) node_kernel(float* __restrict__ out) {
    __shared__ __align__(16) float sB[U16 * HD];   // 512 floats
    __shared__ __align__(16) float sEpi[3 * HD];   // bout | gamma | beta

    // preamble: stage folded params — overlaps edge's tail.
    for (int i = threadIdx.x; i < U16 * HD; i += 256) sB[i] = g_fold[B_OFF + i];
    for (int i = threadIdx.x; i < 3 * HD; i += 256)  sEpi[i] = g_fold[BOUT_OFF + i];
    __syncthreads();

    // wait for edge_kernel's scatter into g_seg
    cudaGridDependencySynchronize();

    int gt   = blockIdx.x * blockDim.x + threadIdx.x;
    int pair = gt >> 2;
    int sub  = gt & 3;
    int n0   = pair * 2;          // NN is even -> n0, n0+1 both valid when n0 < NN
    bool valid = (n0 < NN);
    unsigned mask = 0xffffffffu;

    float s0[U16], s1[U16];
    if (valid) {
        const float4* p0 = reinterpret_cast<const float4*>(&g_seg[(size_t)n0 * U16]);
        const float4* p1 = reinterpret_cast<const float4*>(&g_seg[(size_t)(n0 + 1) * U16]);
#pragma unroll
        for (int k = 0; k < 4; k++) {
            float4 v = p0[k];
            s0[k*4+0]=v.x; s0[k*4+1]=v.y; s0[k*4+2]=v.z; s0[k*4+3]=v.w;
        }
#pragma unroll
        for (int k = 0; k < 4; k++) {
            float4 v = p1[k];
            s1[k*4+0]=v.x; s1[k*4+1]=v.y; s1[k*4+2]=v.z; s1[k*4+3]=v.w;
        }
    } else {
#pragma unroll
        for (int k = 0; k < U16; k++) { s0[k] = 0.f; s1[k] = 0.f; }
    }

    float rinv0 = 1.0f / fmaxf(s0[3] + s0[7] + s0[11] + s0[15], 1.0f);
    float rinv1 = 1.0f / fmaxf(s1[3] + s1[7] + s1[11] + s1[15], 1.0f);

    const int o0 = sub * 8;
    float y0[8], y1[8];
#pragma unroll
    for (int c = 0; c < 8; c++) { y0[c] = 0.f; y1[c] = 0.f; }
#pragma unroll
    for (int j = 0; j < U16; j++) {
        const float4* brow = reinterpret_cast<const float4*>(&sB[j * HD + o0]);
        float4 b0 = brow[0], b1 = brow[1];
        float a0 = s0[j], a1 = s1[j];
        y0[0]=fmaf(a0,b0.x,y0[0]); y0[1]=fmaf(a0,b0.y,y0[1]);
        y0[2]=fmaf(a0,b0.z,y0[2]); y0[3]=fmaf(a0,b0.w,y0[3]);
        y0[4]=fmaf(a0,b1.x,y0[4]); y0[5]=fmaf(a0,b1.y,y0[5]);
        y0[6]=fmaf(a0,b1.z,y0[6]); y0[7]=fmaf(a0,b1.w,y0[7]);
        y1[0]=fmaf(a1,b0.x,y1[0]); y1[1]=fmaf(a1,b0.y,y1[1]);
        y1[2]=fmaf(a1,b0.z,y1[2]); y1[3]=fmaf(a1,b0.w,y1[3]);
        y1[4]=fmaf(a1,b1.x,y1[4]); y1[5]=fmaf(a1,b1.y,y1[5]);
        y1[6]=fmaf(a1,b1.z,y1[6]); y1[7]=fmaf(a1,b1.w,y1[7]);
    }

    float sum0 = 0.f, sum1 = 0.f;
#pragma unroll
    for (int c = 0; c < 8; c++) {
        y0[c] = fmaf(y0[c], rinv0, sEpi[o0 + c]);
        y1[c] = fmaf(y1[c], rinv1, sEpi[o0 + c]);
        sum0 += y0[c]; sum1 += y1[c];
    }
    sum0 += __shfl_xor_sync(mask, sum0, 1);
    sum0 += __shfl_xor_sync(mask, sum0, 2);
    sum1 += __shfl_xor_sync(mask, sum1, 1);
    sum1 += __shfl_xor_sync(mask, sum1, 2);
    float mu0 = sum0 * (1.0f / 32.0f);
    float mu1 = sum1 * (1.0f / 32.0f);

    float sq0 = 0.f, sq1 = 0.f;
#pragma unroll
    for (int c = 0; c < 8; c++) {
        float d0 = y0[c] - mu0; sq0 = fmaf(d0, d0, sq0);
        float d1 = y1[c] - mu1; sq1 = fmaf(d1, d1, sq1);
    }
    sq0 += __shfl_xor_sync(mask, sq0, 1);
    sq0 += __shfl_xor_sync(mask, sq0, 2);
    sq1 += __shfl_xor_sync(mask, sq1, 1);
    sq1 += __shfl_xor_sync(mask, sq1, 2);
    float sf0 = rsqrtf(sq0 * (1.0f / 32.0f) + 1e-5f);
    float sf1 = rsqrtf(sq1 * (1.0f / 32.0f) + 1e-5f);

    if (!valid) return;

    float4* op0 = reinterpret_cast<float4*>(&out[(size_t)n0 * HD + o0]);
    float4* op1 = reinterpret_cast<float4*>(&out[(size_t)(n0 + 1) * HD + o0]);
#pragma unroll
    for (int k = 0; k < 2; k++) {
        float4 v0, v1;
        float* vp0 = &v0.x;
        float* vp1 = &v1.x;
#pragma unroll
        for (int c = 0; c < 4; c++) {
            int o = o0 + k * 4 + c;
            float g = sEpi[HD + o], bt = sEpi[2 * HD + o];
            float x0 = (y0[k*4+c] - mu0) * sf0 * g + bt;
            float x1 = (y1[k*4+c] - mu1) * sf1 * g + bt;
            vp0[c] = x0 / (1.0f + __expf(-x0));
            vp1[c] = x1 / (1.0f + __expf(-x1));
        }
        op0[k] = v0;
        op1[k] = v1;
    }
}

// ---------------- launch ----------------
extern "C" void kernel_launch(void* const* d_in, const int* in_sizes, int n_in,
                              void* d_out, int out_size) {
    const float* pos   = (const float*)d_in[0];
    const int*   edge  = (const int*)d_in[1];
    const float* Wq    = (const float*)d_in[2];
    const float* bq    = (const float*)d_in[3];
    const float* Wk    = (const float*)d_in[4];
    const float* bk    = (const float*)d_in[5];
    const float* Wv    = (const float*)d_in[6];
    const float* bv    = (const float*)d_in[7];
    const float* Wout  = (const float*)d_in[8];
    const float* bout  = (const float*)d_in[9];
    const float* gamma = (const float*)d_in[10];
    const float* beta  = (const float*)d_in[11];
    float* out = (float*)d_out;

    pack_setup_kernel<<<608, 256>>>(pos, edge, Wq, bq, Wk, bk, Wv, bv,
                                    Wout, bout, gamma, beta);

    // PDL: edge overlaps pack's tail; node overlaps edge's tail.
    cudaLaunchAttribute pdl[1];
    pdl[0].id = cudaLaunchAttributeProgrammaticStreamSerialization;
    pdl[0].val.programmaticStreamSerializationAllowed = 1;

    {
        cudaLaunchConfig_t cfg = {};
        cfg.gridDim  = dim3((NE / 2 * 4 + 255) / 256, 1, 1);
        cfg.blockDim = dim3(256, 1, 1);
        cfg.attrs = pdl;
        cfg.numAttrs = 1;
        cudaLaunchKernelEx(&cfg, edge_kernel, edge);
    }
    {
        cudaLaunchConfig_t cfg = {};
        cfg.gridDim  = dim3((NN / 2 * 4 + 255) / 256, 1, 1);
        cfg.blockDim = dim3(256, 1, 1);
        cfg.attrs = pdl;
        cfg.numAttrs = 1;
        cudaLaunchKernelEx(&cfg, node_kernel, out);
    }
}